// round 14
// baseline (speedup 1.0000x reference)
#include <cuda_runtime.h>

// RankingLoss over all pairs, N=8192.
// loss = sum_{i,j: dur_i<dur_j, ev_i==1} max(1-(p_i-p_j),0) / count (0 if count==0).
//
// prep (1 block, 1024 threads): deterministic stable counting sort by 64 duration
//   bins. Count pass -> WARP-PARALLEL per-bin scans (lane=8 slots + shfl scan) ->
//   shfl bin-base scan -> scatter. Emits g_dur/g_pred (bin-sorted) and g_evt
//   {dur, 1-p, lo, hi} (events compacted, sorted). bin() is monotone, so
//   bin_i < bin_j  =>  dur_i < dur_j strictly: suffix [hi,N) needs no compares.
// pair (grid 16 j-splits x 32 event-chunks, 256 threads): thread = one event,
//   SPAN=512 j per block. Exact compare only inside own bin ∩ tile; 3-op/pair
//   unconditional suffix; arithmetic count. Shuffle reduction. Last-arriving
//   block reduces 512 partials in fixed order. Fully deterministic.

#define NN   8192
#define BINS 64
#define PT   1024
#define PPT  (NN / PT)            // 8 rounds
#define PWN  (PT / 32)            // 32 warps
#define RW   (PPT * PWN)          // 256 (round,warp) slots
#define TPB  256
#define NWP  (TPB / 32)           // 8 warps
#define SPAN 512
#define GJ   (NN / SPAN)          // 16
#define GE   (NN / TPB)           // 32 event chunks (covers E up to 8192)
#define NBLK (GJ * GE)            // 512

__device__ float        g_dur[NN];
__device__ float        g_pred[NN];
__device__ float4       g_evt[NN];     // {dur, 1-p, asfloat(lo), asfloat(hi)}
__device__ int          g_E;
__device__ float        g_s[NBLK];
__device__ unsigned int g_c[NBLK];
__device__ unsigned int g_tick = 0u;

__device__ __forceinline__ int dbin(float d) {
    int b = (int)(d * (float)BINS);    // fl(d*64) monotone in d -> bin monotone
    return b < 0 ? 0 : (b > BINS - 1 ? BINS - 1 : b);
}

// ---------------- prep: deterministic counting sort, parallel scans -----------
__global__ void __launch_bounds__(PT)
prep_kernel(const float* __restrict__ preds, const float* __restrict__ targets)
{
    extern __shared__ unsigned short s_cnt[];      // cA[RW*BINS], cE[RW*BINS] = 64KB
    unsigned short* cA = s_cnt;
    unsigned short* cE = s_cnt + RW * BINS;
    __shared__ int totA[BINS], totE[BINS];
    __shared__ int btA[BINS + 1], btE[BINS + 1];

    const int tid = threadIdx.x, wid = tid >> 5, lane = tid & 31;
    const unsigned lt = (1u << lane) - 1u;

    // zero both count arrays (64KB = 16384 u32, 16 stores/thread)
    for (int k = tid; k < RW * BINS; k += PT) ((unsigned int*)s_cnt)[k] = 0u;

    float du[PPT], pr[PPT]; bool evb[PPT]; int bn[PPT];
    #pragma unroll
    for (int r = 0; r < PPT; ++r) {
        const int e = r * PT + tid;
        const float2 tg = ((const float2*)targets)[e];
        du[r]  = tg.x;
        evb[r] = (tg.y == 1.0f);
        pr[r]  = preds[e];
        bn[r]  = dbin(tg.x);
    }
    __syncthreads();

    // count pass: leaders write per-(round,warp,bin) group sizes (distinct slots)
    #pragma unroll
    for (int r = 0; r < PPT; ++r) {
        const int b = bn[r];
        const unsigned mm = __match_any_sync(0xffffffffu, b);
        if (__popc(mm & lt) == 0)
            cA[(r * PWN + wid) * BINS + b] = (unsigned short)__popc(mm);
        const unsigned em  = __ballot_sync(0xffffffffu, evb[r]);
        const unsigned mmE = mm & em;
        if (evb[r] && lane == (__ffs(mmE) - 1))
            cE[(r * PWN + wid) * BINS + b] = (unsigned short)__popc(mmE);
    }
    __syncthreads();

    // warp-parallel per-bin exclusive scans over the 256 slots.
    // warp w: passes 0,1 -> cA bins {2w, 2w+1}; passes 2,3 -> cE bins {2w, 2w+1}.
    #pragma unroll
    for (int pass = 0; pass < 4; ++pass) {
        unsigned short* c = (pass < 2) ? cA : cE;
        const int b = 2 * wid + (pass & 1);
        int v[8], ssum = 0;
        #pragma unroll
        for (int k = 0; k < 8; ++k) {
            v[k] = c[(lane * 8 + k) * BINS + b];
            ssum += v[k];
        }
        int x = ssum;
        #pragma unroll
        for (int o = 1; o < 32; o <<= 1) {
            const int y = __shfl_up_sync(0xffffffffu, x, o);
            if (lane >= o) x += y;
        }
        int acc = x - ssum;                       // exclusive
        #pragma unroll
        for (int k = 0; k < 8; ++k) {
            const int t = v[k];
            c[(lane * 8 + k) * BINS + b] = (unsigned short)acc;
            acc += t;
        }
        if (lane == 31) { if (pass < 2) totA[b] = acc; else totE[b] = acc; }
    }
    __syncthreads();

    // bin-base exclusive scans (warp 0: A, warp 1: E), 2 bins per lane
    if (wid == 0) {
        const int t0 = totA[2 * lane], t1 = totA[2 * lane + 1];
        const int s = t0 + t1;
        int x = s;
        #pragma unroll
        for (int o = 1; o < 32; o <<= 1) {
            const int y = __shfl_up_sync(0xffffffffu, x, o);
            if (lane >= o) x += y;
        }
        const int excl = x - s;
        btA[2 * lane]     = excl;
        btA[2 * lane + 1] = excl + t0;
        if (lane == 31) btA[BINS] = excl + s;
    }
    if (wid == 1) {
        const int t0 = totE[2 * lane], t1 = totE[2 * lane + 1];
        const int s = t0 + t1;
        int x = s;
        #pragma unroll
        for (int o = 1; o < 32; o <<= 1) {
            const int y = __shfl_up_sync(0xffffffffu, x, o);
            if (lane >= o) x += y;
        }
        const int excl = x - s;
        btE[2 * lane]     = excl;
        btE[2 * lane + 1] = excl + t0;
        if (lane == 31) { btE[BINS] = excl + s; g_E = excl + s; }
    }
    __syncthreads();

    // scatter (recomputed match -> identical deterministic ranks)
    #pragma unroll
    for (int r = 0; r < PPT; ++r) {
        const int b = bn[r];
        const unsigned mm = __match_any_sync(0xffffffffu, b);
        const int lr = __popc(mm & lt);
        const int posA = btA[b] + (int)cA[(r * PWN + wid) * BINS + b] + lr;
        g_dur[posA]  = du[r];
        g_pred[posA] = pr[r];
        const unsigned em  = __ballot_sync(0xffffffffu, evb[r]);
        const unsigned mmE = mm & em;
        if (evb[r]) {
            const int lrE  = __popc(mmE & lt);
            const int posE = btE[b] + (int)cE[(r * PWN + wid) * BINS + b] + lrE;
            g_evt[posE] = make_float4(du[r], 1.0f - pr[r],
                                      __int_as_float(btA[b]),
                                      __int_as_float(btA[b + 1]));
        }
    }
}

// ---------------- pair kernel -------------------------------------------------
__global__ void __launch_bounds__(TPB)
pair_kernel(float* __restrict__ out)
{
    __shared__ float sdj[SPAN], spj[SPAN];
    __shared__ float        ws[NWP];
    __shared__ unsigned int wc[NWP];
    __shared__ int s_skip, last_flag;

    const int tid = threadIdx.x, wid = tid >> 5, lane = tid & 31;
    const int j0  = blockIdx.x * SPAN;
    const int i0  = blockIdx.y * TPB;
    const int E   = g_E;

    if (tid == 0) {
        int skip = 1;
        if (i0 < E) {
            const int lo0 = __float_as_int(g_evt[i0].z);   // lo non-decreasing
            skip = (j0 + SPAN <= lo0);
        }
        s_skip = skip;
    }
    __syncthreads();

    float s0 = 0.0f, s1 = 0.0f, s2 = 0.0f, s3 = 0.0f;
    unsigned int cnt = 0u;

    if (!s_skip) {
        // tile load: exactly one LDG.128 + STS.128 per thread
        if (tid < SPAN / 4) {
            ((float4*)sdj)[tid] = ((const float4*)(g_dur + j0))[tid];
        } else {
            const int t = tid - SPAN / 4;
            ((float4*)spj)[t] = ((const float4*)(g_pred + j0))[t];
        }
        __syncthreads();

        const int idx = i0 + tid;
        if (idx < E) {
            const float4 ev = g_evt[idx];
            const float dur = ev.x;
            const float c   = ev.y;
            const int   lo  = __float_as_int(ev.z);
            const int   hi  = __float_as_int(ev.w);

            // exact-compare region: own bin ∩ tile (handles duration ties)
            const int a = max(lo - j0, 0);
            const int b = min(hi - j0, SPAN);
            for (int j = a; j < b; ++j) {
                if (dur < sdj[j]) { s0 += fmaxf(c + spj[j], 0.0f); cnt++; }
            }

            // unconditional suffix: [hi, N) ∩ tile  (3 ops/pair, no compare)
            int f = hi - j0;
            if (f < 0) f = 0;
            if (f < SPAN) {
                cnt += (unsigned int)(SPAN - f);
                for (; (f & 3) != 0 && f < SPAN; ++f)
                    s0 += fmaxf(c + spj[f], 0.0f);
                const float4* sp4 = (const float4*)spj;
                #pragma unroll 4
                for (int t = f >> 2; t < SPAN / 4; ++t) {
                    const float4 P = sp4[t];
                    s0 += fmaxf(c + P.x, 0.0f);
                    s1 += fmaxf(c + P.y, 0.0f);
                    s2 += fmaxf(c + P.z, 0.0f);
                    s3 += fmaxf(c + P.w, 0.0f);
                }
            }
        }
    }

    // shuffle reduction (fixed butterfly order -> deterministic)
    float s = (s0 + s1) + (s2 + s3);
    #pragma unroll
    for (int o = 16; o > 0; o >>= 1) {
        s   += __shfl_xor_sync(0xffffffffu, s, o);
        cnt += __shfl_xor_sync(0xffffffffu, cnt, o);
    }
    if (lane == 0) { ws[wid] = s; wc[wid] = cnt; }
    __syncthreads();

    if (tid == 0) {
        float S = 0.0f; unsigned int C = 0u;
        #pragma unroll
        for (int w = 0; w < NWP; ++w) { S += ws[w]; C += wc[w]; }
        const int slot = blockIdx.y * GJ + blockIdx.x;
        g_s[slot] = S;
        g_c[slot] = C;
        __threadfence();
        last_flag = (atomicAdd(&g_tick, 1u) == NBLK - 1u) ? 1 : 0;
    }
    __syncthreads();

    if (last_flag) {
        __threadfence();
        float        S = g_s[tid] + g_s[tid + TPB];
        unsigned int C = g_c[tid] + g_c[tid + TPB];
        #pragma unroll
        for (int o = 16; o > 0; o >>= 1) {
            S += __shfl_xor_sync(0xffffffffu, S, o);
            C += __shfl_xor_sync(0xffffffffu, C, o);
        }
        if (lane == 0) { ws[wid] = S; wc[wid] = C; }
        __syncthreads();
        if (tid == 0) {
            float SS = 0.0f; unsigned int CC = 0u;
            #pragma unroll
            for (int w = 0; w < NWP; ++w) { SS += ws[w]; CC += wc[w]; }
            out[0] = (CC > 0u) ? (SS / (float)CC) : 0.0f;
            g_tick = 0u;                 // reset for next graph replay
        }
    }
}

extern "C" void kernel_launch(void* const* d_in, const int* in_sizes, int n_in,
                              void* d_out, int out_size)
{
    const float* preds   = (const float*)d_in[0];   // [8192]
    const float* targets = (const float*)d_in[1];   // [8192,2] {dur, ev}
    float* out = (float*)d_out;

    const int prep_smem = 2 * RW * BINS * (int)sizeof(unsigned short);  // 64KB
    cudaFuncSetAttribute(prep_kernel, cudaFuncAttributeMaxDynamicSharedMemorySize,
                         prep_smem);

    prep_kernel<<<1, PT, prep_smem>>>(preds, targets);
    dim3 grid(GJ, GE);
    pair_kernel<<<grid, TPB>>>(out);
}

// round 15
// speedup vs baseline: 4.2437x; 4.2437x over previous
#include <cuda_runtime.h>

// RankingLoss over all pairs, N=8192, single fused kernel (round-6 structure).
// loss = sum_{i,j: dur_i<dur_j, ev_i==1} max(1-(p_i-p_j),0) / count (0 if count==0).
//
// Block = 256 threads owns 512 i-rows (=> ~256 compacted event rows, ALL warps
// work) and one 256-wide j-chunk => 512 blocks. Event rows block-locally
// compacted with an order-preserving ballot scan (deterministic). Unroll-8 inner
// loop, shuffle reductions. Last-arriving block reduces all partials in fixed
// order and writes the output.

#define NN   8192
#define TPB  256
#define IG   512                // i-rows per block (2 compaction rounds)
#define JC   256                // j-cols per block
#define GX   (NN / JC)          // 32
#define GYI  (NN / IG)          // 16
#define NBLK (GX * GYI)         // 512
#define NW   (TPB / 32)         // 8 warps

__device__ float        g_s[NBLK];
__device__ unsigned int g_c[NBLK];
__device__ unsigned int g_tick = 0u;

__global__ void __launch_bounds__(TPB)
pair_kernel(const float* __restrict__ preds, const float* __restrict__ targets,
            float* __restrict__ out)
{
    __shared__ float4 tile4[JC / 2];     // {dur_2t, p_2t, dur_2t+1, p_2t+1}
    __shared__ float  sdur[IG];          // compacted event-row durations
    __shared__ float  scst[IG];          // compacted 1 - p_i
    __shared__ int    wcnt[2 * NW];
    __shared__ float        ws[NW];
    __shared__ unsigned int wcp[NW];
    __shared__ int    last_flag;

    const int tid  = threadIdx.x;
    const int wid  = tid >> 5;
    const int lane = tid & 31;
    const int i0   = blockIdx.y * IG + tid;
    const int i1   = i0 + TPB;
    const int j0   = blockIdx.x * JC;

    // --- load both i-rows, ballot per round ---
    const float2 t0 = ((const float2*)targets)[i0];
    const float2 t1 = ((const float2*)targets)[i1];
    const float  p0 = preds[i0];
    const float  p1 = preds[i1];
    const bool   f0 = (t0.y == 1.0f);
    const bool   f1 = (t1.y == 1.0f);
    const unsigned bm0 = __ballot_sync(0xffffffffu, f0);
    const unsigned bm1 = __ballot_sync(0xffffffffu, f1);
    if (lane == 0) {
        wcnt[wid]      = __popc(bm0);
        wcnt[NW + wid] = __popc(bm1);
    }

    // --- cooperative j-tile load (packed float4) ---
    for (int t = tid; t < JC / 2; t += TPB) {
        const int j = j0 + 2 * t;
        const float2 a = ((const float2*)targets)[j];
        const float2 b = ((const float2*)targets)[j + 1];
        tile4[t] = make_float4(a.x, preds[j], b.x, preds[j + 1]);
    }
    __syncthreads();

    // --- order-preserving prefix over 16 warp-counts ---
    int base0 = 0, base1 = 0, m = 0;
    #pragma unroll
    for (int w = 0; w < NW; ++w) {
        const int c = wcnt[w];
        if (w < wid) base0 += c;
        base1 += c;                      // round-1 bases start after all round-0
        m += c;
    }
    #pragma unroll
    for (int w = 0; w < NW; ++w) {
        const int c = wcnt[NW + w];
        if (w < wid) base1 += c;
        m += c;
    }
    if (f0) {
        const int pos = base0 + __popc(bm0 & ((1u << lane) - 1u));
        sdur[pos] = t0.x;
        scst[pos] = 1.0f - p0;
    }
    if (f1) {
        const int pos = base1 + __popc(bm1 & ((1u << lane) - 1u));
        sdur[pos] = t1.x;
        scst[pos] = 1.0f - p1;
    }
    __syncthreads();

    // --- main loop: all threads grid-stride over compacted rows ---
    float s0 = 0.0f, s1 = 0.0f, s2 = 0.0f, s3 = 0.0f;
    unsigned int c0 = 0u, c1 = 0u;
    for (int r = tid; r < m; r += TPB) {
        const float dur = sdur[r];
        const float c   = scst[r];
        #pragma unroll 8
        for (int t = 0; t < JC / 2; t += 2) {
            const float4 A = tile4[t];
            const float4 B = tile4[t + 1];
            if (dur < A.x) { s0 += fmaxf(c + A.y, 0.0f); c0++; }
            if (dur < A.z) { s1 += fmaxf(c + A.w, 0.0f); c1++; }
            if (dur < B.x) { s2 += fmaxf(c + B.y, 0.0f); c0++; }
            if (dur < B.z) { s3 += fmaxf(c + B.w, 0.0f); c1++; }
        }
    }

    // --- deterministic reduction: warp shuffle + tiny smem stage ---
    float        s   = (s0 + s1) + (s2 + s3);
    unsigned int cnt = c0 + c1;
    #pragma unroll
    for (int o = 16; o > 0; o >>= 1) {
        s   += __shfl_xor_sync(0xffffffffu, s, o);
        cnt += __shfl_xor_sync(0xffffffffu, cnt, o);
    }
    if (lane == 0) { ws[wid] = s; wcp[wid] = cnt; }
    __syncthreads();

    if (tid == 0) {
        float S = 0.0f; unsigned int C = 0u;
        #pragma unroll
        for (int w = 0; w < NW; ++w) { S += ws[w]; C += wcp[w]; }
        const int slot = blockIdx.y * GX + blockIdx.x;
        g_s[slot] = S;
        g_c[slot] = C;
        __threadfence();
        last_flag = (atomicAdd(&g_tick, 1u) == NBLK - 1u) ? 1 : 0;
    }
    __syncthreads();

    if (last_flag) {
        __threadfence();
        // 512 partials -> 256 threads x 2, fixed order: deterministic.
        float        S = g_s[tid] + g_s[tid + TPB];
        unsigned int C = g_c[tid] + g_c[tid + TPB];
        #pragma unroll
        for (int o = 16; o > 0; o >>= 1) {
            S += __shfl_xor_sync(0xffffffffu, S, o);
            C += __shfl_xor_sync(0xffffffffu, C, o);
        }
        if (lane == 0) { ws[wid] = S; wcp[wid] = C; }
        __syncthreads();
        if (tid == 0) {
            float SS = 0.0f; unsigned int CC = 0u;
            #pragma unroll
            for (int w = 0; w < NW; ++w) { SS += ws[w]; CC += wcp[w]; }
            out[0] = (CC > 0u) ? (SS / (float)CC) : 0.0f;
            g_tick = 0u;                 // reset for next graph replay
        }
    }
}

extern "C" void kernel_launch(void* const* d_in, const int* in_sizes, int n_in,
                              void* d_out, int out_size)
{
    const float* preds   = (const float*)d_in[0];   // [8192]
    const float* targets = (const float*)d_in[1];   // [8192,2] {dur, ev}
    float* out = (float*)d_out;

    dim3 grid(GX, GYI);
    pair_kernel<<<grid, TPB>>>(preds, targets, out);
}